// round 8
// baseline (speedup 1.0000x reference)
#include <cuda_runtime.h>

#define LL   9
#define CC   256
#define KK   3
#define VV   25
#define GG   9
#define TT   128
#define NCC  60
#define CINN 3
#define TP   136          // TT + 8 (causal padding)
#define NN   3200         // TT*VV
#define KC   768          // KK*CC
#define KR   2304         // CC*GG  (tconv GEMM K)
#define HSTR 28           // padded row stride for H / Z
#define KCH  32           // tconv k-tile depth
#define KSPL 4            // tconv k-split factor
#define KSEG (KR / KSPL)  // 576 rows per split
#define NSEG (KSEG / KCH) // 18 tiles per split

typedef unsigned long long ull;

__device__ __forceinline__ ull fma2(ull a, ull b, ull c) {
    ull d;
    asm("fma.rn.f32x2 %0, %1, %2, %3;" : "=l"(d) : "l"(a), "l"(b), "l"(c));
    return d;
}
__device__ __forceinline__ ull pack2(float x, float y) {
    ull d;
    asm("mov.b64 %0, {%1, %2};" : "=l"(d) : "f"(x), "f"(y));
    return d;
}
__device__ __forceinline__ float2 unpack2(ull a) {
    float x, y;
    asm("mov.b64 {%0, %1}, %2;" : "=f"(x), "=f"(y) : "l"(a));
    return make_float2(x, y);
}

// ---------------- scratch (device globals) ------------------------------------
__device__ __align__(16) float g_H[2][TT * CC * HSTR];   // activations [t][c][28]
__device__ __align__(16) float g_U[CC * TP * VV];        // relu(LN1(z)), [c][tp][v]
__device__ __align__(16) float g_Z4[KSPL][TT * CC * HSTR]; // tconv k-split partials
__device__ float g_WgT[LL][CC * KC];                     // transposed Wg [l][cp][k*C+c]

// ---------------- block reduce helper (256 threads) ---------------------------
__device__ __forceinline__ float2 ln_stats(float s, float s2, float* sh, float inv_n) {
    int lane = threadIdx.x & 31, wid = threadIdx.x >> 5;
    #pragma unroll
    for (int o = 16; o > 0; o >>= 1) {
        s  += __shfl_down_sync(0xffffffffu, s, o);
        s2 += __shfl_down_sync(0xffffffffu, s2, o);
    }
    if (lane == 0) { sh[wid] = s; sh[8 + wid] = s2; }
    __syncthreads();
    if (threadIdx.x == 0) {
        float ts = 0.f, ts2 = 0.f;
        #pragma unroll
        for (int i = 0; i < 8; i++) { ts += sh[i]; ts2 += sh[8 + i]; }
        float m = ts * inv_n;
        sh[16] = m;
        sh[17] = rsqrtf(ts2 * inv_n - m * m + 1e-5f);
    }
    __syncthreads();
    return make_float2(sh[16], sh[17]);
}

// ---------------- Wg transpose: [l][r][cp] -> [l][cp][r] ----------------------
__global__ void k_wgt(const float* __restrict__ Wg) {
    __shared__ float tile[32][33];
    int l = blockIdx.z;
    int r0 = blockIdx.x * 32, cp0 = blockIdx.y * 32;
    int tx = threadIdx.x, ty = threadIdx.y;
    #pragma unroll
    for (int j = 0; j < 32; j += 8)
        tile[ty + j][tx] = Wg[((size_t)l * KC + r0 + ty + j) * CC + cp0 + tx];
    __syncthreads();
    #pragma unroll
    for (int j = 0; j < 32; j += 8)
        g_WgT[l][(cp0 + ty + j) * KC + r0 + tx] = tile[tx][ty + j];
}

// ---------------- input LN + 1x1 conv (fcn_in) --------------------------------
__global__ void k_input(const float* __restrict__ x, const float* __restrict__ lw,
                        const float* __restrict__ lb, const float* __restrict__ Win,
                        const float* __restrict__ bin) {
    int t = blockIdx.x, tid = threadIdx.x;
    __shared__ float hn[CINN * VV];
    __shared__ float stat[2];
    if (tid < CINN * VV) hn[tid] = x[(tid / VV) * NN + t * VV + (tid % VV)];
    __syncthreads();
    if (tid == 0) {
        float s = 0.f, s2 = 0.f;
        for (int i = 0; i < CINN * VV; i++) { float v = hn[i]; s += v; s2 += v * v; }
        float m = s / (float)(CINN * VV);
        stat[0] = m;
        stat[1] = rsqrtf(s2 / (float)(CINN * VV) - m * m + 1e-5f);
    }
    __syncthreads();
    if (tid < CINN * VV) hn[tid] = (hn[tid] - stat[0]) * stat[1] * lw[tid] + lb[tid];
    __syncthreads();
    float w0 = Win[tid * 3], w1 = Win[tid * 3 + 1], w2 = Win[tid * 3 + 2], b = bin[tid];
    float* Ho = g_H[0];
    #pragma unroll
    for (int v = 0; v < VV; v++)
        Ho[(t * CC + tid) * HSTR + v] =
            fmaf(w0, hn[v], fmaf(w1, hn[VV + v], fmaf(w2, hn[2 * VV + v], b)));
    Ho[(t * CC + tid) * HSTR + 25] = 0.f;
    Ho[(t * CC + tid) * HSTR + 26] = 0.f;
    Ho[(t * CC + tid) * HSTR + 27] = 0.f;
}

// ---- fused: [LN2res of prev layer] + graph conv + bias-via-rowsums + LN1 -----
__global__ void __launch_bounds__(256) k_gcn(
    int l, const float* __restrict__ bgl,
    const float* __restrict__ Aadj, const float* __restrict__ impl,
    const float* __restrict__ lw1, const float* __restrict__ lb1,
    const float* __restrict__ btp, const float* __restrict__ lw2,
    const float* __restrict__ lb2) {
    int tid = threadIdx.x;
    if (blockIdx.x == TT) {
        for (int i = tid; i < CC * 8 * VV; i += 256) {
            int c = i / (8 * VV), r = i % (8 * VV);
            g_U[c * TP * VV + r] = fmaxf(lb1[c * VV + (r % VV)], 0.f);
        }
        return;
    }
    int t = blockIdx.x;
    __shared__ __align__(16) float Hs[CC * HSTR];     // [cp][v pad28]
    __shared__ __align__(16) float As[KK * VV * 28];  // [k][v][w pad28]
    __shared__ float Ss[KK * VV];
    __shared__ float red[18];
    int c = tid;

    for (int i = tid; i < KK * VV * 28; i += 256) {
        int kv = i / 28, w = i - kv * 28;
        As[i] = (w < VV) ? Aadj[kv * VV + w] * impl[kv * VV + w] : 0.f;
    }

    if (l == 0) {
        const float* Hp = g_H[0] + t * CC * HSTR;
        for (int i = tid; i < CC * HSTR; i += 256) Hs[i] = Hp[i];
    } else {
        // ---- sum k-split z partials; +bias; LN2; residual; ReLU --------------
        float z[28];
        {
            const float4* z0 = reinterpret_cast<const float4*>(&g_Z4[0][(t * CC + c) * HSTR]);
            const float4* z1 = reinterpret_cast<const float4*>(&g_Z4[1][(t * CC + c) * HSTR]);
            const float4* z2 = reinterpret_cast<const float4*>(&g_Z4[2][(t * CC + c) * HSTR]);
            const float4* z3 = reinterpret_cast<const float4*>(&g_Z4[3][(t * CC + c) * HSTR]);
            #pragma unroll
            for (int j = 0; j < 7; j++) {
                float4 a = z0[j], b = z1[j], d = z2[j], e = z3[j];
                z[4 * j]     = (a.x + b.x) + (d.x + e.x);
                z[4 * j + 1] = (a.y + b.y) + (d.y + e.y);
                z[4 * j + 2] = (a.z + b.z) + (d.z + e.z);
                z[4 * j + 3] = (a.w + b.w) + (d.w + e.w);
            }
        }
        float btv = btp[c];
        float s = 0.f, s2 = 0.f;
        #pragma unroll
        for (int w = 0; w < VV; w++) {
            z[w] += btv;
            s += z[w]; s2 += z[w] * z[w];
        }
        float2 st = ln_stats(s, s2, red, 1.f / (float)(CC * VV));
        const float* Hi = g_H[(l - 1) & 1];
        float* Ho = g_H[l & 1];
        #pragma unroll
        for (int w = 0; w < VV; w++) {
            float val = (z[w] - st.x) * st.y * lw2[c * VV + w] + lb2[c * VV + w];
            float res = (t >= 4) ? Hi[((t - 4) * CC + c) * HSTR + w] : 0.f;
            float h = fmaxf(val + res, 0.f);
            Ho[(t * CC + c) * HSTR + w] = h;
            Hs[c * HSTR + w] = h;
        }
        Hs[c * HSTR + 25] = 0.f;
        Hs[c * HSTR + 26] = 0.f;
        Hs[c * HSTR + 27] = 0.f;
    }
    __syncthreads();
    if (tid < KK * VV) {
        int k = tid / VV, w = tid - k * VV;
        float s = 0.f;
        #pragma unroll
        for (int v = 0; v < VV; v++) s += As[(k * VV + v) * 28 + w];
        Ss[tid] = s;
    }

    // ---- Y[k][v] = sum_cp WgT[cp][k*C+c] * H[cp][v]  (f32x2 over v-pairs) ----
    const float* WT = g_WgT[l];
    ull Y0[13], Y1[13], Y2[13];
    #pragma unroll
    for (int j = 0; j < 13; j++) { Y0[j] = 0ull; Y1[j] = 0ull; Y2[j] = 0ull; }
    #pragma unroll 4
    for (int cp = 0; cp < CC; cp++) {
        const float* wp = WT + cp * KC;
        float w0 = wp[c], w1 = wp[CC + c], w2 = wp[2 * CC + c];
        ull p0 = pack2(w0, w0), p1 = pack2(w1, w1), p2 = pack2(w2, w2);
        const ull* hr = reinterpret_cast<const ull*>(&Hs[cp * HSTR]);
        #pragma unroll
        for (int j = 0; j < 13; j++) {
            ull h = hr[j];
            Y0[j] = fma2(p0, h, Y0[j]);
            Y1[j] = fma2(p1, h, Y1[j]);
            Y2[j] = fma2(p2, h, Y2[j]);
        }
    }
    float y[KK][VV + 1];
    #pragma unroll
    for (int j = 0; j < 13; j++) {
        float2 a = unpack2(Y0[j]); y[0][2 * j] = a.x; y[0][2 * j + 1] = a.y;
        float2 b = unpack2(Y1[j]); y[1][2 * j] = b.x; y[1][2 * j + 1] = b.y;
        float2 d = unpack2(Y2[j]); y[2][2 * j] = d.x; y[2][2 * j + 1] = d.y;
    }
    __syncthreads();   // Ss ready

    // ---- z[w] = sum_k sum_v y[k][v] * As[k][v][w] ----------------------------
    ull zacc[14];
    #pragma unroll
    for (int j = 0; j < 14; j++) zacc[j] = 0ull;
    #pragma unroll
    for (int k = 0; k < KK; k++) {
        for (int v = 0; v < VV; v++) {
            ull yy = pack2(y[k][v], y[k][v]);
            const ull* ar = reinterpret_cast<const ull*>(&As[(k * VV + v) * 28]);
            #pragma unroll
            for (int j = 0; j < 14; j++) zacc[j] = fma2(yy, ar[j], zacc[j]);
        }
    }
    float z[VV + 3];
    #pragma unroll
    for (int j = 0; j < 14; j++) {
        float2 a = unpack2(zacc[j]);
        z[2 * j] = a.x;
        if (2 * j + 1 < VV + 3) z[2 * j + 1] = a.y;
    }
    float b0 = bgl[c], b1 = bgl[CC + c], b2 = bgl[2 * CC + c];
    float s = 0.f, s2 = 0.f;
    #pragma unroll
    for (int w = 0; w < VV; w++) {
        z[w] += b0 * Ss[w] + b1 * Ss[VV + w] + b2 * Ss[2 * VV + w];
        s += z[w]; s2 += z[w] * z[w];
    }
    float2 st = ln_stats(s, s2, red, 1.f / (float)(CC * VV));
    #pragma unroll
    for (int w = 0; w < VV; w++) {
        float u = (z[w] - st.x) * st.y * lw1[c * VV + w] + lb1[c * VV + w];
        g_U[c * TP * VV + (t + 8) * VV + w] = fmaxf(u, 0.f);
    }
}

// ------- tconv im2col SGEMM, k-split x4 ---------------------------------------
// C_part[kz][256 x 3200] = Wt[:, kz*576:(kz+1)*576] @ B[same k-rows]
// B[(c,g)][n] = g_U[c*TP*25 + (8-g)*25 + n].  64x64 tile, 4o x 4n microtile.
__global__ void __launch_bounds__(256) k_tconv(const float* __restrict__ Wtl) {
    __shared__ __align__(16) ull As2[KCH][66];    // (w,w) pairs  [kk][o]
    __shared__ __align__(16) float Bs[KCH][64];   // [kk][n]
    __shared__ int Boff[KSEG];                    // precomputed U row offsets
    int n0 = blockIdx.x * 64, o0 = blockIdx.y * 64;
    int kz = blockIdx.z;
    int kbase = kz * KSEG;
    int tid = threadIdx.x, tx = tid & 15, ty = tid >> 4;

    for (int i = tid; i < KSEG; i += 256) {
        int r = kbase + i;
        int c = r / GG, g = r - c * GG;
        Boff[i] = c * (TP * VV) + (8 - g) * VV + n0;
    }

    ull acc[4][2];
    #pragma unroll
    for (int i = 0; i < 4; i++) { acc[i][0] = 0ull; acc[i][1] = 0ull; }
    __syncthreads();

    for (int rt = 0; rt < NSEG; rt++) {
        int r0 = rt * KCH;
        int idx = tid;
        #pragma unroll
        for (int it = 0; it < 8; it++, idx += 256) {
            float w = Wtl[(o0 + (idx >> 5)) * KR + kbase + r0 + (idx & 31)];
            As2[idx & 31][idx >> 5] = pack2(w, w);
        }
        idx = tid;
        #pragma unroll
        for (int it = 0; it < 8; it++, idx += 256) {
            Bs[idx >> 6][idx & 63] = g_U[Boff[r0 + (idx >> 6)] + (idx & 63)];
        }
        __syncthreads();
        #pragma unroll
        for (int kk = 0; kk < KCH; kk++) {
            ulonglong2 a01 = *reinterpret_cast<const ulonglong2*>(&As2[kk][ty * 4]);
            ulonglong2 a23 = *reinterpret_cast<const ulonglong2*>(&As2[kk][ty * 4 + 2]);
            ulonglong2 b   = *reinterpret_cast<const ulonglong2*>(&Bs[kk][tx * 4]);
            acc[0][0] = fma2(a01.x, b.x, acc[0][0]);
            acc[0][1] = fma2(a01.x, b.y, acc[0][1]);
            acc[1][0] = fma2(a01.y, b.x, acc[1][0]);
            acc[1][1] = fma2(a01.y, b.y, acc[1][1]);
            acc[2][0] = fma2(a23.x, b.x, acc[2][0]);
            acc[2][1] = fma2(a23.x, b.y, acc[2][1]);
            acc[3][0] = fma2(a23.y, b.x, acc[3][0]);
            acc[3][1] = fma2(a23.y, b.y, acc[3][1]);
        }
        __syncthreads();
    }
    float* Zp = g_Z4[kz];
    #pragma unroll
    for (int i = 0; i < 4; i++) {
        int o = o0 + ty * 4 + i;
        #pragma unroll
        for (int j = 0; j < 2; j++) {
            int n = n0 + tx * 4 + 2 * j;
            float2 p = unpack2(acc[i][j]);
            int t = n / VV, v = n - t * VV;
            Zp[(t * CC + o) * HSTR + v] = p.x;
            n++;
            t = n / VV; v = n - t * VV;
            Zp[(t * CC + o) * HSTR + v] = p.y;
        }
    }
}

// ------- final: z + LN2 + residual + ReLU + pool + classify -------------------
__global__ void __launch_bounds__(256) k_out(
    const float* __restrict__ btp, const float* __restrict__ lw2,
    const float* __restrict__ lb2, const float* __restrict__ Wout,
    const float* __restrict__ bout, float* __restrict__ out) {
    int t = blockIdx.x, c = threadIdx.x;
    __shared__ float red[18];
    __shared__ float pooled[CC];
    float z[28];
    {
        const float4* z0 = reinterpret_cast<const float4*>(&g_Z4[0][(t * CC + c) * HSTR]);
        const float4* z1 = reinterpret_cast<const float4*>(&g_Z4[1][(t * CC + c) * HSTR]);
        const float4* z2 = reinterpret_cast<const float4*>(&g_Z4[2][(t * CC + c) * HSTR]);
        const float4* z3 = reinterpret_cast<const float4*>(&g_Z4[3][(t * CC + c) * HSTR]);
        #pragma unroll
        for (int j = 0; j < 7; j++) {
            float4 a = z0[j], b = z1[j], d = z2[j], e = z3[j];
            z[4 * j]     = (a.x + b.x) + (d.x + e.x);
            z[4 * j + 1] = (a.y + b.y) + (d.y + e.y);
            z[4 * j + 2] = (a.z + b.z) + (d.z + e.z);
            z[4 * j + 3] = (a.w + b.w) + (d.w + e.w);
        }
    }
    float btv = btp[c];
    float s = 0.f, s2 = 0.f;
    #pragma unroll
    for (int w = 0; w < VV; w++) { z[w] += btv; s += z[w]; s2 += z[w] * z[w]; }
    float2 st = ln_stats(s, s2, red, 1.f / (float)(CC * VV));
    // layer-8 INPUT: written by k_gcn(l=8) to g_H[8&1] = g_H[0]
    const float* Hi = g_H[0];
    float acc = 0.f;
    #pragma unroll
    for (int w = 0; w < VV; w++) {
        float val = (z[w] - st.x) * st.y * lw2[c * VV + w] + lb2[c * VV + w];
        float res = (t >= 4) ? Hi[((t - 4) * CC + c) * HSTR + w] : 0.f;
        acc += fmaxf(val + res, 0.f);
    }
    pooled[c] = acc * (1.f / (float)VV);
    __syncthreads();
    if (c < NCC) {
        float a = bout[c];
        for (int q = 0; q < CC; q++) a = fmaf(Wout[c * CC + q], pooled[q], a);
        out[t * NCC + c] = a;
    }
}

// ------------------------------- launcher -------------------------------------
extern "C" void kernel_launch(void* const* d_in, const int* in_sizes, int n_in,
                              void* d_out, int out_size) {
    const float* x    = (const float*)d_in[0];
    const float* Aadj = (const float*)d_in[1];
    const float* lniw = (const float*)d_in[2];
    const float* lnib = (const float*)d_in[3];
    const float* Win  = (const float*)d_in[4];
    const float* bin  = (const float*)d_in[5];
    const float* Wg   = (const float*)d_in[6];
    const float* bg   = (const float*)d_in[7];
    const float* ln1w = (const float*)d_in[8];
    const float* ln1b = (const float*)d_in[9];
    const float* Wt   = (const float*)d_in[10];
    const float* bt   = (const float*)d_in[11];
    const float* ln2w = (const float*)d_in[12];
    const float* ln2b = (const float*)d_in[13];
    const float* imp  = (const float*)d_in[14];
    const float* Wout = (const float*)d_in[15];
    const float* bout = (const float*)d_in[16];
    float* out = (float*)d_out;

    k_wgt<<<dim3(24, 8, LL), dim3(32, 8)>>>(Wg);
    k_input<<<TT, 256>>>(x, lniw, lnib, Win, bin);
    for (int l = 0; l < LL; l++) {
        int p = (l > 0) ? (l - 1) : 0;
        k_gcn<<<TT + 1, 256>>>(l, bg + l * KC, Aadj, imp + l * KK * VV * VV,
                               ln1w + l * CC * VV, ln1b + l * CC * VV,
                               bt + p * CC, ln2w + p * CC * VV, ln2b + p * CC * VV);
        k_tconv<<<dim3(50, 4, KSPL), 256>>>(Wt + (size_t)l * CC * KR);
    }
    k_out<<<TT, 256>>>(bt + 8 * CC, ln2w + 8 * CC * VV, ln2b + 8 * CC * VV,
                       Wout, bout, out);
}

// round 9
// speedup vs baseline: 1.5505x; 1.5505x over previous
#include <cuda_runtime.h>

#define LL   9
#define CC   256
#define KK   3
#define VV   25
#define GG   9
#define TT   128
#define NCC  60
#define CINN 3
#define TP   136          // TT + 8 (causal padding)
#define NN   3200         // TT*VV
#define KC   768          // KK*CC
#define KR   2304         // CC*GG  (tconv GEMM K)
#define HSTR 28           // padded row stride for H / Z
#define KCH  32           // tconv k-tile depth
#define KSPL 3            // tconv k-split factor
#define KSEG (KR / KSPL)  // 768 rows per split
#define NSEG (KSEG / KCH) // 24 tiles per split

typedef unsigned long long ull;

__device__ __forceinline__ ull fma2(ull a, ull b, ull c) {
    ull d;
    asm("fma.rn.f32x2 %0, %1, %2, %3;" : "=l"(d) : "l"(a), "l"(b), "l"(c));
    return d;
}
__device__ __forceinline__ ull pack2(float x, float y) {
    ull d;
    asm("mov.b64 %0, {%1, %2};" : "=l"(d) : "f"(x), "f"(y));
    return d;
}
__device__ __forceinline__ float2 unpack2(ull a) {
    float x, y;
    asm("mov.b64 {%0, %1}, %2;" : "=f"(x), "=f"(y) : "l"(a));
    return make_float2(x, y);
}

// ---------------- scratch (device globals) ------------------------------------
__device__ __align__(16) float g_H[2][TT * CC * HSTR];     // activations [t][c][28]
__device__ __align__(16) float g_U[CC * TP * VV];          // relu(LN1(z)), [c][tp][v]
__device__ __align__(16) float g_Z3[KSPL][TT * CC * HSTR]; // tconv k-split partials
__device__ float g_WgT[LL][CC * KC];                       // transposed Wg [l][cp][k*C+c]
__device__ ull   g_WtT[LL][KR * CC];                       // transposed+packed Wt [l][k][o]

// ---------------- block reduce helper (256 threads) ---------------------------
__device__ __forceinline__ float2 ln_stats(float s, float s2, float* sh, float inv_n) {
    int lane = threadIdx.x & 31, wid = threadIdx.x >> 5;
    #pragma unroll
    for (int o = 16; o > 0; o >>= 1) {
        s  += __shfl_down_sync(0xffffffffu, s, o);
        s2 += __shfl_down_sync(0xffffffffu, s2, o);
    }
    if (lane == 0) { sh[wid] = s; sh[8 + wid] = s2; }
    __syncthreads();
    if (threadIdx.x == 0) {
        float ts = 0.f, ts2 = 0.f;
        #pragma unroll
        for (int i = 0; i < 8; i++) { ts += sh[i]; ts2 += sh[8 + i]; }
        float m = ts * inv_n;
        sh[16] = m;
        sh[17] = rsqrtf(ts2 * inv_n - m * m + 1e-5f);
    }
    __syncthreads();
    return make_float2(sh[16], sh[17]);
}

// ---------------- Wg transpose: [l][r][cp] -> [l][cp][r] ----------------------
__global__ void k_wgt(const float* __restrict__ Wg) {
    __shared__ float tile[32][33];
    int l = blockIdx.z;
    int r0 = blockIdx.x * 32, cp0 = blockIdx.y * 32;
    int tx = threadIdx.x, ty = threadIdx.y;
    #pragma unroll
    for (int j = 0; j < 32; j += 8)
        tile[ty + j][tx] = Wg[((size_t)l * KC + r0 + ty + j) * CC + cp0 + tx];
    __syncthreads();
    #pragma unroll
    for (int j = 0; j < 32; j += 8)
        g_WgT[l][(cp0 + ty + j) * KC + r0 + tx] = tile[tx][ty + j];
}

// ------------ Wt transpose+pack: [l][o][k] -> [l][k][o] as (w,w) ull ----------
__global__ void k_wtt(const float* __restrict__ Wt) {
    __shared__ float tile[32][33];
    int l = blockIdx.z;
    int k0 = blockIdx.x * 32, o0 = blockIdx.y * 32;
    int tx = threadIdx.x, ty = threadIdx.y;
    #pragma unroll
    for (int j = 0; j < 32; j += 8)
        tile[ty + j][tx] = Wt[((size_t)l * CC + o0 + ty + j) * KR + k0 + tx];
    __syncthreads();
    #pragma unroll
    for (int j = 0; j < 32; j += 8) {
        float w = tile[tx][ty + j];
        g_WtT[l][(size_t)(k0 + ty + j) * CC + o0 + tx] = pack2(w, w);
    }
}

// ---------------- input LN + 1x1 conv (fcn_in) --------------------------------
__global__ void k_input(const float* __restrict__ x, const float* __restrict__ lw,
                        const float* __restrict__ lb, const float* __restrict__ Win,
                        const float* __restrict__ bin) {
    int t = blockIdx.x, tid = threadIdx.x;
    __shared__ float hn[CINN * VV];
    __shared__ float stat[2];
    if (tid < CINN * VV) hn[tid] = x[(tid / VV) * NN + t * VV + (tid % VV)];
    __syncthreads();
    if (tid == 0) {
        float s = 0.f, s2 = 0.f;
        for (int i = 0; i < CINN * VV; i++) { float v = hn[i]; s += v; s2 += v * v; }
        float m = s / (float)(CINN * VV);
        stat[0] = m;
        stat[1] = rsqrtf(s2 / (float)(CINN * VV) - m * m + 1e-5f);
    }
    __syncthreads();
    if (tid < CINN * VV) hn[tid] = (hn[tid] - stat[0]) * stat[1] * lw[tid] + lb[tid];
    __syncthreads();
    float w0 = Win[tid * 3], w1 = Win[tid * 3 + 1], w2 = Win[tid * 3 + 2], b = bin[tid];
    float* Ho = g_H[0];
    #pragma unroll
    for (int v = 0; v < VV; v++)
        Ho[(t * CC + tid) * HSTR + v] =
            fmaf(w0, hn[v], fmaf(w1, hn[VV + v], fmaf(w2, hn[2 * VV + v], b)));
    Ho[(t * CC + tid) * HSTR + 25] = 0.f;
    Ho[(t * CC + tid) * HSTR + 26] = 0.f;
    Ho[(t * CC + tid) * HSTR + 27] = 0.f;
}

// ---- fused: [LN2res of prev layer] + graph conv + bias-via-rowsums + LN1 -----
__global__ void __launch_bounds__(256) k_gcn(
    int l, const float* __restrict__ bgl,
    const float* __restrict__ Aadj, const float* __restrict__ impl,
    const float* __restrict__ lw1, const float* __restrict__ lb1,
    const float* __restrict__ btp, const float* __restrict__ lw2,
    const float* __restrict__ lb2) {
    int tid = threadIdx.x;
    if (blockIdx.x == TT) {
        for (int i = tid; i < CC * 8 * VV; i += 256) {
            int c = i / (8 * VV), r = i % (8 * VV);
            g_U[c * TP * VV + r] = fmaxf(lb1[c * VV + (r % VV)], 0.f);
        }
        return;
    }
    int t = blockIdx.x;
    __shared__ __align__(16) float Hs[CC * HSTR];     // [cp][v pad28]
    __shared__ __align__(16) float As[KK * VV * 28];  // [k][v][w pad28]
    __shared__ float Ss[KK * VV];
    __shared__ float red[18];
    int c = tid;

    for (int i = tid; i < KK * VV * 28; i += 256) {
        int kv = i / 28, w = i - kv * 28;
        As[i] = (w < VV) ? Aadj[kv * VV + w] * impl[kv * VV + w] : 0.f;
    }

    if (l == 0) {
        const float* Hp = g_H[0] + t * CC * HSTR;
        for (int i = tid; i < CC * HSTR; i += 256) Hs[i] = Hp[i];
    } else {
        // ---- sum k-split z partials; +bias; LN2; residual; ReLU --------------
        float z[28];
        {
            const float4* z0 = reinterpret_cast<const float4*>(&g_Z3[0][(t * CC + c) * HSTR]);
            const float4* z1 = reinterpret_cast<const float4*>(&g_Z3[1][(t * CC + c) * HSTR]);
            const float4* z2 = reinterpret_cast<const float4*>(&g_Z3[2][(t * CC + c) * HSTR]);
            #pragma unroll
            for (int j = 0; j < 7; j++) {
                float4 a = z0[j], b = z1[j], d = z2[j];
                z[4 * j]     = a.x + b.x + d.x;
                z[4 * j + 1] = a.y + b.y + d.y;
                z[4 * j + 2] = a.z + b.z + d.z;
                z[4 * j + 3] = a.w + b.w + d.w;
            }
        }
        float btv = btp[c];
        float s = 0.f, s2 = 0.f;
        #pragma unroll
        for (int w = 0; w < VV; w++) {
            z[w] += btv;
            s += z[w]; s2 += z[w] * z[w];
        }
        float2 st = ln_stats(s, s2, red, 1.f / (float)(CC * VV));
        const float* Hi = g_H[(l - 1) & 1];
        float* Ho = g_H[l & 1];
        #pragma unroll
        for (int w = 0; w < VV; w++) {
            float val = (z[w] - st.x) * st.y * lw2[c * VV + w] + lb2[c * VV + w];
            float res = (t >= 4) ? Hi[((t - 4) * CC + c) * HSTR + w] : 0.f;
            float h = fmaxf(val + res, 0.f);
            Ho[(t * CC + c) * HSTR + w] = h;
            Hs[c * HSTR + w] = h;
        }
        Hs[c * HSTR + 25] = 0.f;
        Hs[c * HSTR + 26] = 0.f;
        Hs[c * HSTR + 27] = 0.f;
    }
    __syncthreads();
    if (tid < KK * VV) {
        int k = tid / VV, w = tid - k * VV;
        float s = 0.f;
        #pragma unroll
        for (int v = 0; v < VV; v++) s += As[(k * VV + v) * 28 + w];
        Ss[tid] = s;
    }

    // ---- Y[k][v] = sum_cp WgT[cp][k*C+c] * H[cp][v]  (f32x2 over v-pairs) ----
    const float* WT = g_WgT[l];
    ull Y0[13], Y1[13], Y2[13];
    #pragma unroll
    for (int j = 0; j < 13; j++) { Y0[j] = 0ull; Y1[j] = 0ull; Y2[j] = 0ull; }
    #pragma unroll 4
    for (int cp = 0; cp < CC; cp++) {
        const float* wp = WT + cp * KC;
        float w0 = wp[c], w1 = wp[CC + c], w2 = wp[2 * CC + c];
        ull p0 = pack2(w0, w0), p1 = pack2(w1, w1), p2 = pack2(w2, w2);
        const ull* hr = reinterpret_cast<const ull*>(&Hs[cp * HSTR]);
        #pragma unroll
        for (int j = 0; j < 13; j++) {
            ull h = hr[j];
            Y0[j] = fma2(p0, h, Y0[j]);
            Y1[j] = fma2(p1, h, Y1[j]);
            Y2[j] = fma2(p2, h, Y2[j]);
        }
    }
    float y[KK][VV + 1];
    #pragma unroll
    for (int j = 0; j < 13; j++) {
        float2 a = unpack2(Y0[j]); y[0][2 * j] = a.x; y[0][2 * j + 1] = a.y;
        float2 b = unpack2(Y1[j]); y[1][2 * j] = b.x; y[1][2 * j + 1] = b.y;
        float2 d = unpack2(Y2[j]); y[2][2 * j] = d.x; y[2][2 * j + 1] = d.y;
    }
    __syncthreads();   // Ss ready

    // ---- z[w] = sum_k sum_v y[k][v] * As[k][v][w] ----------------------------
    ull zacc[14];
    #pragma unroll
    for (int j = 0; j < 14; j++) zacc[j] = 0ull;
    #pragma unroll
    for (int k = 0; k < KK; k++) {
        for (int v = 0; v < VV; v++) {
            ull yy = pack2(y[k][v], y[k][v]);
            const ull* ar = reinterpret_cast<const ull*>(&As[(k * VV + v) * 28]);
            #pragma unroll
            for (int j = 0; j < 14; j++) zacc[j] = fma2(yy, ar[j], zacc[j]);
        }
    }
    float z[VV + 3];
    #pragma unroll
    for (int j = 0; j < 14; j++) {
        float2 a = unpack2(zacc[j]);
        z[2 * j] = a.x;
        if (2 * j + 1 < VV + 3) z[2 * j + 1] = a.y;
    }
    float b0 = bgl[c], b1 = bgl[CC + c], b2 = bgl[2 * CC + c];
    float s = 0.f, s2 = 0.f;
    #pragma unroll
    for (int w = 0; w < VV; w++) {
        z[w] += b0 * Ss[w] + b1 * Ss[VV + w] + b2 * Ss[2 * VV + w];
        s += z[w]; s2 += z[w] * z[w];
    }
    float2 st = ln_stats(s, s2, red, 1.f / (float)(CC * VV));
    #pragma unroll
    for (int w = 0; w < VV; w++) {
        float u = (z[w] - st.x) * st.y * lw1[c * VV + w] + lb1[c * VV + w];
        g_U[c * TP * VV + (t + 8) * VV + w] = fmaxf(u, 0.f);
    }
}

// ------- tconv im2col SGEMM: 64o x 128n tile, 4o x 8n microtile, k-split x3 ---
// C_part[kz] = WtT[kz-rows][o] @ B;  B[(c,g)][n] = g_U[c*TP*25 + (8-g)*25 + n].
__global__ void __launch_bounds__(256) k_tconv(int l) {
    __shared__ __align__(16) ull  As2[KCH][64];    // [kk][o] pre-packed (w,w)
    __shared__ __align__(16) float Bs[KCH][128];   // [kk][n]
    __shared__ int Boff[KSEG];
    int n0 = blockIdx.x * 128, o0 = blockIdx.y * 64;
    int kz = blockIdx.z;
    int kbase = kz * KSEG;
    int tid = threadIdx.x, tx = tid & 15, ty = tid >> 4;

    for (int i = tid; i < KSEG; i += 256) {
        int r = kbase + i;
        int c = r / GG, g = r - c * GG;
        Boff[i] = c * (TP * VV) + (8 - g) * VV + n0;
    }
    ull acc[4][4];
    #pragma unroll
    for (int i = 0; i < 4; i++)
        #pragma unroll
        for (int j = 0; j < 4; j++) acc[i][j] = 0ull;
    __syncthreads();

    const ull* WT = g_WtT[l] + (size_t)kbase * CC;
    for (int rt = 0; rt < NSEG; rt++) {
        int r0 = rt * KCH;
        // A fill: 2048 ull = 1024 ull2 slots, 4 per thread (LDG.128 -> STS.128)
        int idx = tid;
        #pragma unroll
        for (int it = 0; it < 4; it++, idx += 256) {
            int kk = idx >> 5, oj = (idx & 31) * 2;
            ulonglong2 w = *reinterpret_cast<const ulonglong2*>(
                WT + (size_t)(r0 + kk) * CC + o0 + oj);
            *reinterpret_cast<ulonglong2*>(&As2[kk][oj]) = w;
        }
        // B fill: 4096 floats = 1024 float4 slots, 4 per thread
        idx = tid;
        #pragma unroll
        for (int it = 0; it < 4; it++, idx += 256) {
            int kk = idx >> 5, j4 = (idx & 31) * 4;
            const float* src = g_U + Boff[r0 + kk] + j4;
            float4 f = make_float4(src[0], src[1], src[2], src[3]);
            *reinterpret_cast<float4*>(&Bs[kk][j4]) = f;
        }
        __syncthreads();
        #pragma unroll
        for (int kk = 0; kk < KCH; kk++) {
            ulonglong2 a01 = *reinterpret_cast<const ulonglong2*>(&As2[kk][ty * 4]);
            ulonglong2 a23 = *reinterpret_cast<const ulonglong2*>(&As2[kk][ty * 4 + 2]);
            ulonglong2 b01 = *reinterpret_cast<const ulonglong2*>(&Bs[kk][tx * 8]);
            ulonglong2 b23 = *reinterpret_cast<const ulonglong2*>(&Bs[kk][tx * 8 + 4]);
            acc[0][0] = fma2(a01.x, b01.x, acc[0][0]);
            acc[0][1] = fma2(a01.x, b01.y, acc[0][1]);
            acc[0][2] = fma2(a01.x, b23.x, acc[0][2]);
            acc[0][3] = fma2(a01.x, b23.y, acc[0][3]);
            acc[1][0] = fma2(a01.y, b01.x, acc[1][0]);
            acc[1][1] = fma2(a01.y, b01.y, acc[1][1]);
            acc[1][2] = fma2(a01.y, b23.x, acc[1][2]);
            acc[1][3] = fma2(a01.y, b23.y, acc[1][3]);
            acc[2][0] = fma2(a23.x, b01.x, acc[2][0]);
            acc[2][1] = fma2(a23.x, b01.y, acc[2][1]);
            acc[2][2] = fma2(a23.x, b23.x, acc[2][2]);
            acc[2][3] = fma2(a23.x, b23.y, acc[2][3]);
            acc[3][0] = fma2(a23.y, b01.x, acc[3][0]);
            acc[3][1] = fma2(a23.y, b01.y, acc[3][1]);
            acc[3][2] = fma2(a23.y, b23.x, acc[3][2]);
            acc[3][3] = fma2(a23.y, b23.y, acc[3][3]);
        }
        __syncthreads();
    }
    float* Zp = g_Z3[kz];
    #pragma unroll
    for (int i = 0; i < 4; i++) {
        int o = o0 + ty * 4 + i;
        #pragma unroll
        for (int j = 0; j < 4; j++) {
            int n = n0 + tx * 8 + 2 * j;
            float2 p = unpack2(acc[i][j]);
            int t = n / VV, v = n - t * VV;
            Zp[(t * CC + o) * HSTR + v] = p.x;
            n++;
            t = n / VV; v = n - t * VV;
            Zp[(t * CC + o) * HSTR + v] = p.y;
        }
    }
}

// ------- final: z + LN2 + residual + ReLU + pool + classify -------------------
__global__ void __launch_bounds__(256) k_out(
    const float* __restrict__ btp, const float* __restrict__ lw2,
    const float* __restrict__ lb2, const float* __restrict__ Wout,
    const float* __restrict__ bout, float* __restrict__ out) {
    int t = blockIdx.x, c = threadIdx.x;
    __shared__ float red[18];
    __shared__ float pooled[CC];
    float z[28];
    {
        const float4* z0 = reinterpret_cast<const float4*>(&g_Z3[0][(t * CC + c) * HSTR]);
        const float4* z1 = reinterpret_cast<const float4*>(&g_Z3[1][(t * CC + c) * HSTR]);
        const float4* z2 = reinterpret_cast<const float4*>(&g_Z3[2][(t * CC + c) * HSTR]);
        #pragma unroll
        for (int j = 0; j < 7; j++) {
            float4 a = z0[j], b = z1[j], d = z2[j];
            z[4 * j]     = a.x + b.x + d.x;
            z[4 * j + 1] = a.y + b.y + d.y;
            z[4 * j + 2] = a.z + b.z + d.z;
            z[4 * j + 3] = a.w + b.w + d.w;
        }
    }
    float btv = btp[c];
    float s = 0.f, s2 = 0.f;
    #pragma unroll
    for (int w = 0; w < VV; w++) { z[w] += btv; s += z[w]; s2 += z[w] * z[w]; }
    float2 st = ln_stats(s, s2, red, 1.f / (float)(CC * VV));
    // layer-8 INPUT: written by k_gcn(l=8) to g_H[8&1] = g_H[0]
    const float* Hi = g_H[0];
    float acc = 0.f;
    #pragma unroll
    for (int w = 0; w < VV; w++) {
        float val = (z[w] - st.x) * st.y * lw2[c * VV + w] + lb2[c * VV + w];
        float res = (t >= 4) ? Hi[((t - 4) * CC + c) * HSTR + w] : 0.f;
        acc += fmaxf(val + res, 0.f);
    }
    pooled[c] = acc * (1.f / (float)VV);
    __syncthreads();
    if (c < NCC) {
        float a = bout[c];
        for (int q = 0; q < CC; q++) a = fmaf(Wout[c * CC + q], pooled[q], a);
        out[t * NCC + c] = a;
    }
}

// ------------------------------- launcher -------------------------------------
extern "C" void kernel_launch(void* const* d_in, const int* in_sizes, int n_in,
                              void* d_out, int out_size) {
    const float* x    = (const float*)d_in[0];
    const float* Aadj = (const float*)d_in[1];
    const float* lniw = (const float*)d_in[2];
    const float* lnib = (const float*)d_in[3];
    const float* Win  = (const float*)d_in[4];
    const float* bin  = (const float*)d_in[5];
    const float* Wg   = (const float*)d_in[6];
    const float* bg   = (const float*)d_in[7];
    const float* ln1w = (const float*)d_in[8];
    const float* ln1b = (const float*)d_in[9];
    const float* Wt   = (const float*)d_in[10];
    const float* bt   = (const float*)d_in[11];
    const float* ln2w = (const float*)d_in[12];
    const float* ln2b = (const float*)d_in[13];
    const float* imp  = (const float*)d_in[14];
    const float* Wout = (const float*)d_in[15];
    const float* bout = (const float*)d_in[16];
    float* out = (float*)d_out;

    k_wgt<<<dim3(24, 8, LL), dim3(32, 8)>>>(Wg);
    k_wtt<<<dim3(72, 8, LL), dim3(32, 8)>>>(Wt);
    k_input<<<TT, 256>>>(x, lniw, lnib, Win, bin);
    for (int l = 0; l < LL; l++) {
        int p = (l > 0) ? (l - 1) : 0;
        k_gcn<<<TT + 1, 256>>>(l, bg + l * KC, Aadj, imp + l * KK * VV * VV,
                               ln1w + l * CC * VV, ln1b + l * CC * VV,
                               bt + p * CC, ln2w + p * CC * VV, ln2b + p * CC * VV);
        k_tconv<<<dim3(25, 4, KSPL), 256>>>(l);
    }
    k_out<<<TT, 256>>>(bt + 8 * CC, ln2w + 8 * CC * VV, ln2b + 8 * CC * VV,
                       Wout, bout, out);
}

// round 13
// speedup vs baseline: 1.9623x; 1.2655x over previous
#include <cuda_runtime.h>

#define LL   9
#define CC   256
#define KK   3
#define VV   25
#define GG   9
#define TT   128
#define NCC  60
#define CINN 3
#define TP   136          // TT + 8 (causal padding)
#define NN   3200         // TT*VV
#define KC   768          // KK*CC
#define KR   2304         // CC*GG  (tconv GEMM K)
#define HSTR 28           // padded row stride for H / Z
#define KCH  24           // tconv k-tile depth
#define KSPL 6            // tconv k-split factor
#define KSEG (KR / KSPL)  // 384 rows per split
#define NSEG (KSEG / KCH) // 16 tiles per split

typedef unsigned long long ull;

__device__ __forceinline__ ull fma2(ull a, ull b, ull c) {
    ull d;
    asm("fma.rn.f32x2 %0, %1, %2, %3;" : "=l"(d) : "l"(a), "l"(b), "l"(c));
    return d;
}
__device__ __forceinline__ ull pack2(float x, float y) {
    ull d;
    asm("mov.b64 %0, {%1, %2};" : "=l"(d) : "f"(x), "f"(y));
    return d;
}
__device__ __forceinline__ float2 unpack2(ull a) {
    float x, y;
    asm("mov.b64 {%0, %1}, %2;" : "=f"(x), "=f"(y) : "l"(a));
    return make_float2(x, y);
}

// ---------------- scratch (device globals) ------------------------------------
__device__ __align__(16) float g_H[2][TT * CC * HSTR];     // activations [t][c][28]
__device__ __align__(16) float g_U[CC * TP * VV];          // relu(LN1(z)), [c][tp][v]
__device__ __align__(16) float g_Z6[KSPL][TT * CC * HSTR]; // tconv k-split partials
__device__ float g_WgT[LL][CC * KC];                       // transposed Wg [l][cp][k*C+c]
__device__ ull   g_WtT[LL][KR * CC];                       // transposed+packed Wt [l][k][o]

// ------------- block reduce for 512 threads (16 warps) ------------------------
__device__ __forceinline__ float2 ln_stats16(float s, float s2, float* sh, float inv_n) {
    int lane = threadIdx.x & 31, wid = threadIdx.x >> 5;
    #pragma unroll
    for (int o = 16; o > 0; o >>= 1) {
        s  += __shfl_down_sync(0xffffffffu, s, o);
        s2 += __shfl_down_sync(0xffffffffu, s2, o);
    }
    if (lane == 0) { sh[wid] = s; sh[16 + wid] = s2; }
    __syncthreads();
    if (threadIdx.x == 0) {
        float ts = 0.f, ts2 = 0.f;
        #pragma unroll
        for (int i = 0; i < 16; i++) { ts += sh[i]; ts2 += sh[16 + i]; }
        float m = ts * inv_n;
        sh[32] = m;
        sh[33] = rsqrtf(ts2 * inv_n - m * m + 1e-5f);
    }
    __syncthreads();
    return make_float2(sh[32], sh[33]);
}

// ------------- block reduce for 256 threads (8 warps) -------------------------
__device__ __forceinline__ float2 ln_stats8(float s, float s2, float* sh, float inv_n) {
    int lane = threadIdx.x & 31, wid = threadIdx.x >> 5;
    #pragma unroll
    for (int o = 16; o > 0; o >>= 1) {
        s  += __shfl_down_sync(0xffffffffu, s, o);
        s2 += __shfl_down_sync(0xffffffffu, s2, o);
    }
    if (lane == 0) { sh[wid] = s; sh[8 + wid] = s2; }
    __syncthreads();
    if (threadIdx.x == 0) {
        float ts = 0.f, ts2 = 0.f;
        #pragma unroll
        for (int i = 0; i < 8; i++) { ts += sh[i]; ts2 += sh[8 + i]; }
        float m = ts * inv_n;
        sh[16] = m;
        sh[17] = rsqrtf(ts2 * inv_n - m * m + 1e-5f);
    }
    __syncthreads();
    return make_float2(sh[16], sh[17]);
}

// ---------------- Wg transpose: [l][r][cp] -> [l][cp][r] ----------------------
__global__ void k_wgt(const float* __restrict__ Wg) {
    __shared__ float tile[32][33];
    int l = blockIdx.z;
    int r0 = blockIdx.x * 32, cp0 = blockIdx.y * 32;
    int tx = threadIdx.x, ty = threadIdx.y;
    #pragma unroll
    for (int j = 0; j < 32; j += 8)
        tile[ty + j][tx] = Wg[((size_t)l * KC + r0 + ty + j) * CC + cp0 + tx];
    __syncthreads();
    #pragma unroll
    for (int j = 0; j < 32; j += 8)
        g_WgT[l][(cp0 + ty + j) * KC + r0 + tx] = tile[tx][ty + j];
}

// ------------ Wt transpose+pack: [l][o][k] -> [l][k][o] as (w,w) ull ----------
__global__ void k_wtt(const float* __restrict__ Wt) {
    __shared__ float tile[32][33];
    int l = blockIdx.z;
    int k0 = blockIdx.x * 32, o0 = blockIdx.y * 32;
    int tx = threadIdx.x, ty = threadIdx.y;
    #pragma unroll
    for (int j = 0; j < 32; j += 8)
        tile[ty + j][tx] = Wt[((size_t)l * CC + o0 + ty + j) * KR + k0 + tx];
    __syncthreads();
    #pragma unroll
    for (int j = 0; j < 32; j += 8) {
        float w = tile[tx][ty + j];
        g_WtT[l][(size_t)(k0 + ty + j) * CC + o0 + tx] = pack2(w, w);
    }
}

// ---------------- input LN + 1x1 conv (fcn_in) --------------------------------
__global__ void k_input(const float* __restrict__ x, const float* __restrict__ lw,
                        const float* __restrict__ lb, const float* __restrict__ Win,
                        const float* __restrict__ bin) {
    int t = blockIdx.x, tid = threadIdx.x;
    __shared__ float hn[CINN * VV];
    __shared__ float stat[2];
    if (tid < CINN * VV) hn[tid] = x[(tid / VV) * NN + t * VV + (tid % VV)];
    __syncthreads();
    if (tid == 0) {
        float s = 0.f, s2 = 0.f;
        for (int i = 0; i < CINN * VV; i++) { float v = hn[i]; s += v; s2 += v * v; }
        float m = s / (float)(CINN * VV);
        stat[0] = m;
        stat[1] = rsqrtf(s2 / (float)(CINN * VV) - m * m + 1e-5f);
    }
    __syncthreads();
    if (tid < CINN * VV) hn[tid] = (hn[tid] - stat[0]) * stat[1] * lw[tid] + lb[tid];
    __syncthreads();
    float w0 = Win[tid * 3], w1 = Win[tid * 3 + 1], w2 = Win[tid * 3 + 2], b = bin[tid];
    float* Ho = g_H[0];
    #pragma unroll
    for (int v = 0; v < VV; v++)
        Ho[(t * CC + tid) * HSTR + v] =
            fmaf(w0, hn[v], fmaf(w1, hn[VV + v], fmaf(w2, hn[2 * VV + v], b)));
    Ho[(t * CC + tid) * HSTR + 25] = 0.f;
    Ho[(t * CC + tid) * HSTR + 26] = 0.f;
    Ho[(t * CC + tid) * HSTR + 27] = 0.f;
}

// ---- fused per-frame pipeline, 512 threads: thread = (channel, v-half) -------
__global__ void __launch_bounds__(512) k_gcn(
    int l, const float* __restrict__ bgl,
    const float* __restrict__ Aadj, const float* __restrict__ impl,
    const float* __restrict__ lw1, const float* __restrict__ lb1,
    const float* __restrict__ btp, const float* __restrict__ lw2,
    const float* __restrict__ lb2) {
    int tid = threadIdx.x;
    if (blockIdx.x == TT) {
        for (int i = tid; i < CC * 8 * VV; i += 512) {
            int c = i / (8 * VV), r = i % (8 * VV);
            g_U[c * TP * VV + r] = fmaxf(lb1[c * VV + (r % VV)], 0.f);
        }
        return;
    }
    int t = blockIdx.x;
    __shared__ __align__(16) float Hs[CC * HSTR];     // [cp][v pad28]; reused as Zs
    __shared__ __align__(16) float As[KK * VV * 28];  // [k][v][w pad28]
    __shared__ float Ss[KK * VV];
    __shared__ float red[34];
    int c = tid & 255;
    int hv = tid >> 8;       // v-half: 0 -> v 0..13, 1 -> v 14..27

    for (int i = tid; i < KK * VV * 28; i += 512) {
        int kv = i / 28, w = i - kv * 28;
        As[i] = (w < VV) ? Aadj[kv * VV + w] * impl[kv * VV + w] : 0.f;
    }

    if (l == 0) {
        const float* Hp = g_H[0] + t * CC * HSTR;
        for (int i = tid; i < CC * HSTR; i += 512) Hs[i] = Hp[i];
    } else {
        // ---- sum 6 k-split z partials; +bias; LN2; residual; ReLU (half 0) ---
        float z[28];
        float s = 0.f, s2 = 0.f;
        if (hv == 0) {
            float btv = btp[c];
            #pragma unroll
            for (int w = 0; w < 28; w++) z[w] = 0.f;
            #pragma unroll
            for (int p = 0; p < KSPL; p++) {
                const float4* zr =
                    reinterpret_cast<const float4*>(&g_Z6[p][(t * CC + c) * HSTR]);
                #pragma unroll
                for (int j = 0; j < 7; j++) {
                    float4 f = zr[j];
                    z[4 * j] += f.x; z[4 * j + 1] += f.y;
                    z[4 * j + 2] += f.z; z[4 * j + 3] += f.w;
                }
            }
            #pragma unroll
            for (int w = 0; w < VV; w++) {
                z[w] += btv;
                s += z[w]; s2 += z[w] * z[w];
            }
        }
        float2 st = ln_stats16(s, s2, red, 1.f / (float)(CC * VV));
        if (hv == 0) {
            const float* Hi = g_H[(l - 1) & 1];
            float* Ho = g_H[l & 1];
            #pragma unroll
            for (int w = 0; w < VV; w++) {
                float val = (z[w] - st.x) * st.y * lw2[c * VV + w] + lb2[c * VV + w];
                float res = (t >= 4) ? Hi[((t - 4) * CC + c) * HSTR + w] : 0.f;
                float h = fmaxf(val + res, 0.f);
                Ho[(t * CC + c) * HSTR + w] = h;
                Hs[c * HSTR + w] = h;
            }
            Hs[c * HSTR + 25] = 0.f;
            Hs[c * HSTR + 26] = 0.f;
            Hs[c * HSTR + 27] = 0.f;
        }
    }
    __syncthreads();
    if (tid < KK * VV) {
        int k = tid / VV, w = tid - k * VV;
        float s = 0.f;
        #pragma unroll
        for (int v = 0; v < VV; v++) s += As[(k * VV + v) * 28 + w];
        Ss[tid] = s;
    }

    // ---- Y[k][v-half] = sum_cp WgT[cp][k*C+c] * H[cp][v-half] ----------------
    const float* WT = g_WgT[l];
    ull Y0[7], Y1[7], Y2[7];
    #pragma unroll
    for (int j = 0; j < 7; j++) { Y0[j] = 0ull; Y1[j] = 0ull; Y2[j] = 0ull; }
    const ull* hbase = reinterpret_cast<const ull*>(Hs) + hv * 7;
    #pragma unroll 4
    for (int cp = 0; cp < CC; cp++) {
        const float* wp = WT + cp * KC;
        float w0 = wp[c], w1 = wp[CC + c], w2 = wp[2 * CC + c];
        ull p0 = pack2(w0, w0), p1 = pack2(w1, w1), p2 = pack2(w2, w2);
        const ull* hr = hbase + cp * 14;
        #pragma unroll
        for (int j = 0; j < 7; j++) {
            ull h = hr[j];
            Y0[j] = fma2(p0, h, Y0[j]);
            Y1[j] = fma2(p1, h, Y1[j]);
            Y2[j] = fma2(p2, h, Y2[j]);
        }
    }
    float y[KK][14];
    #pragma unroll
    for (int j = 0; j < 7; j++) {
        float2 a = unpack2(Y0[j]); y[0][2 * j] = a.x; y[0][2 * j + 1] = a.y;
        float2 b = unpack2(Y1[j]); y[1][2 * j] = b.x; y[1][2 * j + 1] = b.y;
        float2 d = unpack2(Y2[j]); y[2][2 * j] = d.x; y[2][2 * j + 1] = d.y;
    }
    __syncthreads();   // Ss ready; Hs reads done -> can be reused as Zs

    // ---- z_partial[w] = sum_k sum_{v in half} y * As[k][v][w] ----------------
    ull zacc[14];
    #pragma unroll
    for (int j = 0; j < 14; j++) zacc[j] = 0ull;
    int vbase = hv * 14;
    int vcnt = hv ? 11 : 14;   // half 1 covers v=14..24 (25..27 are zero-pad)
    #pragma unroll
    for (int k = 0; k < KK; k++) {
        for (int vl = 0; vl < vcnt; vl++) {
            float yv = y[k][vl];
            ull yy = pack2(yv, yv);
            const ull* ar = reinterpret_cast<const ull*>(&As[(k * VV + vbase + vl) * 28]);
            #pragma unroll
            for (int j = 0; j < 14; j++) zacc[j] = fma2(yy, ar[j], zacc[j]);
        }
    }
    float zp[28];
    #pragma unroll
    for (int j = 0; j < 14; j++) {
        float2 a = unpack2(zacc[j]);
        zp[2 * j] = a.x; zp[2 * j + 1] = a.y;
    }
    float* Zs = Hs;   // alias: Hs dead after Y loop
    if (hv == 1) {
        #pragma unroll
        for (int j = 0; j < 7; j++)
            *reinterpret_cast<float4*>(&Zs[c * 28 + 4 * j]) =
                make_float4(zp[4 * j], zp[4 * j + 1], zp[4 * j + 2], zp[4 * j + 3]);
    }
    __syncthreads();
    float s = 0.f, s2 = 0.f;
    float zf[VV];
    if (hv == 0) {
        float b0 = bgl[c], b1 = bgl[CC + c], b2 = bgl[2 * CC + c];
        #pragma unroll
        for (int w = 0; w < VV; w++) {
            float v = zp[w] + Zs[c * 28 + w]
                    + b0 * Ss[w] + b1 * Ss[VV + w] + b2 * Ss[2 * VV + w];
            zf[w] = v;
            s += v; s2 += v * v;
        }
    }
    float2 st = ln_stats16(s, s2, red, 1.f / (float)(CC * VV));
    if (hv == 0) {
        #pragma unroll
        for (int w = 0; w < VV; w++) {
            float u = (zf[w] - st.x) * st.y * lw1[c * VV + w] + lb1[c * VV + w];
            g_U[c * TP * VV + (t + 8) * VV + w] = fmaxf(u, 0.f);
        }
    }
}

// ------- tconv im2col SGEMM: 128o x 128n tile, 8o x 8n microtile, k-split x6 --
// C_part[kz] = WtT[kz-rows][o] @ B;  B[(c,g)][n] = g_U[c*TP*25 + (8-g)*25 + n].
__global__ void __launch_bounds__(256, 2) k_tconv(int l) {
    __shared__ __align__(16) ull  As2[KCH][128];   // [kk][o] pre-packed (w,w)
    __shared__ __align__(16) float Bs[KCH][128];   // [kk][n]
    __shared__ int Boff[KSEG];
    int n0 = blockIdx.x * 128, o0 = blockIdx.y * 128;
    int kz = blockIdx.z;
    int kbase = kz * KSEG;
    int tid = threadIdx.x, tx = tid & 15, ty = tid >> 4;

    for (int i = tid; i < KSEG; i += 256) {
        int r = kbase + i;
        int c = r / GG, g = r - c * GG;
        Boff[i] = c * (TP * VV) + (8 - g) * VV + n0;
    }
    ull acc[8][4];
    #pragma unroll
    for (int i = 0; i < 8; i++)
        #pragma unroll
        for (int j = 0; j < 4; j++) acc[i][j] = 0ull;
    __syncthreads();

    const ull* WT = g_WtT[l] + (size_t)kbase * CC;
    for (int rt = 0; rt < NSEG; rt++) {
        int r0 = rt * KCH;
        // A fill: 24x128 ull = 1536 ull2, 6 per thread (coalesced 16B LDG/STS)
        int idx = tid;
        #pragma unroll
        for (int it = 0; it < 6; it++, idx += 256) {
            int kk = idx >> 6, oj = (idx & 63) * 2;
            ulonglong2 w = *reinterpret_cast<const ulonglong2*>(
                WT + (size_t)(r0 + kk) * CC + o0 + oj);
            *reinterpret_cast<ulonglong2*>(&As2[kk][oj]) = w;
        }
        // B fill: 24x128 floats = 768 float4-slots, 3 per thread (scalar gather)
        idx = tid;
        #pragma unroll
        for (int it = 0; it < 3; it++, idx += 256) {
            int kk = idx >> 5, j4 = (idx & 31) * 4;
            const float* src = g_U + Boff[r0 + kk] + j4;
            *reinterpret_cast<float4*>(&Bs[kk][j4]) =
                make_float4(src[0], src[1], src[2], src[3]);
        }
        __syncthreads();
        #pragma unroll
        for (int kk = 0; kk < KCH; kk++) {
            ulonglong2 a01 = *reinterpret_cast<const ulonglong2*>(&As2[kk][ty * 8]);
            ulonglong2 a23 = *reinterpret_cast<const ulonglong2*>(&As2[kk][ty * 8 + 2]);
            ulonglong2 a45 = *reinterpret_cast<const ulonglong2*>(&As2[kk][ty * 8 + 4]);
            ulonglong2 a67 = *reinterpret_cast<const ulonglong2*>(&As2[kk][ty * 8 + 6]);
            ulonglong2 b01 = *reinterpret_cast<const ulonglong2*>(&Bs[kk][tx * 8]);
            ulonglong2 b23 = *reinterpret_cast<const ulonglong2*>(&Bs[kk][tx * 8 + 4]);
            ull av[8] = {a01.x, a01.y, a23.x, a23.y, a45.x, a45.y, a67.x, a67.y};
            ull bv[4] = {b01.x, b01.y, b23.x, b23.y};
            #pragma unroll
            for (int i = 0; i < 8; i++)
                #pragma unroll
                for (int j = 0; j < 4; j++)
                    acc[i][j] = fma2(av[i], bv[j], acc[i][j]);
        }
        __syncthreads();
    }
    float* Zp = g_Z6[kz];
    #pragma unroll
    for (int i = 0; i < 8; i++) {
        int o = o0 + ty * 8 + i;
        #pragma unroll
        for (int j = 0; j < 4; j++) {
            int n = n0 + tx * 8 + 2 * j;
            float2 p = unpack2(acc[i][j]);
            int t = n / VV, v = n - t * VV;
            Zp[(t * CC + o) * HSTR + v] = p.x;
            n++;
            t = n / VV; v = n - t * VV;
            Zp[(t * CC + o) * HSTR + v] = p.y;
        }
    }
}

// ------- final: z + LN2 + residual + ReLU + pool + classify -------------------
__global__ void __launch_bounds__(256) k_out(
    const float* __restrict__ btp, const float* __restrict__ lw2,
    const float* __restrict__ lb2, const float* __restrict__ Wout,
    const float* __restrict__ bout, float* __restrict__ out) {
    int t = blockIdx.x, c = threadIdx.x;
    __shared__ float red[18];
    __shared__ float pooled[CC];
    float z[28];
    #pragma unroll
    for (int w = 0; w < 28; w++) z[w] = 0.f;
    #pragma unroll
    for (int p = 0; p < KSPL; p++) {
        const float4* zr = reinterpret_cast<const float4*>(&g_Z6[p][(t * CC + c) * HSTR]);
        #pragma unroll
        for (int j = 0; j < 7; j++) {
            float4 f = zr[j];
            z[4 * j] += f.x; z[4 * j + 1] += f.y;
            z[4 * j + 2] += f.z; z[4 * j + 3] += f.w;
        }
    }
    float btv = btp[c];
    float s = 0.f, s2 = 0.f;
    #pragma unroll
    for (int w = 0; w < VV; w++) { z[w] += btv; s += z[w]; s2 += z[w] * z[w]; }
    float2 st = ln_stats8(s, s2, red, 1.f / (float)(CC * VV));
    // layer-8 INPUT: written by k_gcn(l=8) to g_H[8&1] = g_H[0]
    const float* Hi = g_H[0];
    float acc = 0.f;
    #pragma unroll
    for (int w = 0; w < VV; w++) {
        float val = (z[w] - st.x) * st.y * lw2[c * VV + w] + lb2[c * VV + w];
        float res = (t >= 4) ? Hi[((t - 4) * CC + c) * HSTR + w] : 0.f;
        acc += fmaxf(val + res, 0.f);
    }
    pooled[c] = acc * (1.f / (float)VV);
    __syncthreads();
    if (c < NCC) {
        float a = bout[c];
        for (int q = 0; q < CC; q++) a = fmaf(Wout[c * CC + q], pooled[q], a);
        out[t * NCC + c] = a;
    }
}

// ------------------------------- launcher -------------------------------------
extern "C" void kernel_launch(void* const* d_in, const int* in_sizes, int n_in,
                              void* d_out, int out_size) {
    const float* x    = (const float*)d_in[0];
    const float* Aadj = (const float*)d_in[1];
    const float* lniw = (const float*)d_in[2];
    const float* lnib = (const float*)d_in[3];
    const float* Win  = (const float*)d_in[4];
    const float* bin  = (const float*)d_in[5];
    const float* Wg   = (const float*)d_in[6];
    const float* bg   = (const float*)d_in[7];
    const float* ln1w = (const float*)d_in[8];
    const float* ln1b = (const float*)d_in[9];
    const float* Wt   = (const float*)d_in[10];
    const float* bt   = (const float*)d_in[11];
    const float* ln2w = (const float*)d_in[12];
    const float* ln2b = (const float*)d_in[13];
    const float* imp  = (const float*)d_in[14];
    const float* Wout = (const float*)d_in[15];
    const float* bout = (const float*)d_in[16];
    float* out = (float*)d_out;

    k_wgt<<<dim3(24, 8, LL), dim3(32, 8)>>>(Wg);
    k_wtt<<<dim3(72, 8, LL), dim3(32, 8)>>>(Wt);
    k_input<<<TT, 256>>>(x, lniw, lnib, Win, bin);
    for (int l = 0; l < LL; l++) {
        int p = (l > 0) ? (l - 1) : 0;
        k_gcn<<<TT + 1, 512>>>(l, bg + l * KC, Aadj, imp + l * KK * VV * VV,
                               ln1w + l * CC * VV, ln1b + l * CC * VV,
                               bt + p * CC, ln2w + p * CC * VV, ln2b + p * CC * VV);
        k_tconv<<<dim3(25, 2, KSPL), 256>>>(l);
    }
    k_out<<<TT, 256>>>(bt + 8 * CC, ln2w + 8 * CC * VV, ln2b + 8 * CC * VV,
                       Wout, bout, out);
}

// round 14
// speedup vs baseline: 2.0416x; 1.0404x over previous
#include <cuda_runtime.h>

#define LL   9
#define CC   256
#define KK   3
#define VV   25
#define GG   9
#define TT   128
#define NCC  60
#define CINN 3
#define TP   136          // TT + 8 (causal padding)
#define NN   3200         // TT*VV
#define KC   768          // KK*CC
#define KR   2304         // CC*GG  (tconv GEMM K)
#define HSTR 28           // padded row stride for H / Z
#define KCH  16           // tconv k-tile depth (double-buffered)
#define KSPL 6            // tconv k-split factor
#define KSEG (KR / KSPL)  // 384 rows per split
#define NSEG (KSEG / KCH) // 24 tiles per split

// gcn dynamic smem layout (floats)
#define GHS 0                 // Hs: CC*HSTR = 7168
#define GAS 7168              // As: 2100
#define GSS 9268              // Ss: 75
#define GRD 9344              // red: 34
#define GWS 9384              // Ws: 2 x 8*KC = 12288
#define GSM_FLOATS (GWS + 12288)
#define GSM_BYTES  (GSM_FLOATS * 4)

typedef unsigned long long ull;

__device__ __forceinline__ ull fma2(ull a, ull b, ull c) {
    ull d;
    asm("fma.rn.f32x2 %0, %1, %2, %3;" : "=l"(d) : "l"(a), "l"(b), "l"(c));
    return d;
}
__device__ __forceinline__ ull pack2(float x, float y) {
    ull d;
    asm("mov.b64 %0, {%1, %2};" : "=l"(d) : "f"(x), "f"(y));
    return d;
}
__device__ __forceinline__ float2 unpack2(ull a) {
    float x, y;
    asm("mov.b64 {%0, %1}, %2;" : "=f"(x), "=f"(y) : "l"(a));
    return make_float2(x, y);
}

// ---------------- scratch (device globals) ------------------------------------
__device__ __align__(16) float g_H[2][TT * CC * HSTR];     // activations [t][c][28]
__device__ __align__(16) float g_U[CC * TP * VV];          // relu(LN1(z)), [c][tp][v]
__device__ __align__(16) float g_Z6[KSPL][TT * CC * HSTR]; // tconv k-split partials
__device__ float g_WgT[LL][CC * KC];                       // transposed Wg [l][cp][k*C+c]
__device__ ull   g_WtT[LL][KR * CC];                       // transposed+packed Wt [l][k][o]

// ------------- block reduce for 512 threads (16 warps) ------------------------
__device__ __forceinline__ float2 ln_stats16(float s, float s2, float* sh, float inv_n) {
    int lane = threadIdx.x & 31, wid = threadIdx.x >> 5;
    #pragma unroll
    for (int o = 16; o > 0; o >>= 1) {
        s  += __shfl_down_sync(0xffffffffu, s, o);
        s2 += __shfl_down_sync(0xffffffffu, s2, o);
    }
    if (lane == 0) { sh[wid] = s; sh[16 + wid] = s2; }
    __syncthreads();
    if (threadIdx.x == 0) {
        float ts = 0.f, ts2 = 0.f;
        #pragma unroll
        for (int i = 0; i < 16; i++) { ts += sh[i]; ts2 += sh[16 + i]; }
        float m = ts * inv_n;
        sh[32] = m;
        sh[33] = rsqrtf(ts2 * inv_n - m * m + 1e-5f);
    }
    __syncthreads();
    return make_float2(sh[32], sh[33]);
}

// ------------- block reduce for 256 threads (8 warps) -------------------------
__device__ __forceinline__ float2 ln_stats8(float s, float s2, float* sh, float inv_n) {
    int lane = threadIdx.x & 31, wid = threadIdx.x >> 5;
    #pragma unroll
    for (int o = 16; o > 0; o >>= 1) {
        s  += __shfl_down_sync(0xffffffffu, s, o);
        s2 += __shfl_down_sync(0xffffffffu, s2, o);
    }
    if (lane == 0) { sh[wid] = s; sh[8 + wid] = s2; }
    __syncthreads();
    if (threadIdx.x == 0) {
        float ts = 0.f, ts2 = 0.f;
        #pragma unroll
        for (int i = 0; i < 8; i++) { ts += sh[i]; ts2 += sh[8 + i]; }
        float m = ts * inv_n;
        sh[16] = m;
        sh[17] = rsqrtf(ts2 * inv_n - m * m + 1e-5f);
    }
    __syncthreads();
    return make_float2(sh[16], sh[17]);
}

// ---------------- Wg transpose: [l][r][cp] -> [l][cp][r] ----------------------
__global__ void k_wgt(const float* __restrict__ Wg) {
    __shared__ float tile[32][33];
    int l = blockIdx.z;
    int r0 = blockIdx.x * 32, cp0 = blockIdx.y * 32;
    int tx = threadIdx.x, ty = threadIdx.y;
    #pragma unroll
    for (int j = 0; j < 32; j += 8)
        tile[ty + j][tx] = Wg[((size_t)l * KC + r0 + ty + j) * CC + cp0 + tx];
    __syncthreads();
    #pragma unroll
    for (int j = 0; j < 32; j += 8)
        g_WgT[l][(cp0 + ty + j) * KC + r0 + tx] = tile[tx][ty + j];
}

// ------------ Wt transpose+pack: [l][o][k] -> [l][k][o] as (w,w) ull ----------
__global__ void k_wtt(const float* __restrict__ Wt) {
    __shared__ float tile[32][33];
    int l = blockIdx.z;
    int k0 = blockIdx.x * 32, o0 = blockIdx.y * 32;
    int tx = threadIdx.x, ty = threadIdx.y;
    #pragma unroll
    for (int j = 0; j < 32; j += 8)
        tile[ty + j][tx] = Wt[((size_t)l * CC + o0 + ty + j) * KR + k0 + tx];
    __syncthreads();
    #pragma unroll
    for (int j = 0; j < 32; j += 8) {
        float w = tile[tx][ty + j];
        g_WtT[l][(size_t)(k0 + ty + j) * CC + o0 + tx] = pack2(w, w);
    }
}

// ---------------- input LN + 1x1 conv (fcn_in) --------------------------------
__global__ void k_input(const float* __restrict__ x, const float* __restrict__ lw,
                        const float* __restrict__ lb, const float* __restrict__ Win,
                        const float* __restrict__ bin) {
    int t = blockIdx.x, tid = threadIdx.x;
    __shared__ float hn[CINN * VV];
    __shared__ float stat[2];
    if (tid < CINN * VV) hn[tid] = x[(tid / VV) * NN + t * VV + (tid % VV)];
    __syncthreads();
    if (tid == 0) {
        float s = 0.f, s2 = 0.f;
        for (int i = 0; i < CINN * VV; i++) { float v = hn[i]; s += v; s2 += v * v; }
        float m = s / (float)(CINN * VV);
        stat[0] = m;
        stat[1] = rsqrtf(s2 / (float)(CINN * VV) - m * m + 1e-5f);
    }
    __syncthreads();
    if (tid < CINN * VV) hn[tid] = (hn[tid] - stat[0]) * stat[1] * lw[tid] + lb[tid];
    __syncthreads();
    float w0 = Win[tid * 3], w1 = Win[tid * 3 + 1], w2 = Win[tid * 3 + 2], b = bin[tid];
    float* Ho = g_H[0];
    #pragma unroll
    for (int v = 0; v < VV; v++)
        Ho[(t * CC + tid) * HSTR + v] =
            fmaf(w0, hn[v], fmaf(w1, hn[VV + v], fmaf(w2, hn[2 * VV + v], b)));
    Ho[(t * CC + tid) * HSTR + 25] = 0.f;
    Ho[(t * CC + tid) * HSTR + 26] = 0.f;
    Ho[(t * CC + tid) * HSTR + 27] = 0.f;
}

// ---- fused per-frame pipeline, 512 threads, smem-staged weights --------------
__global__ void __launch_bounds__(512) k_gcn(
    int l, const float* __restrict__ bgl,
    const float* __restrict__ Aadj, const float* __restrict__ impl,
    const float* __restrict__ lw1, const float* __restrict__ lb1,
    const float* __restrict__ btp, const float* __restrict__ lw2,
    const float* __restrict__ lb2) {
    int tid = threadIdx.x;
    if (blockIdx.x == TT) {
        for (int i = tid; i < CC * 8 * VV; i += 512) {
            int c = i / (8 * VV), r = i % (8 * VV);
            g_U[c * TP * VV + r] = fmaxf(lb1[c * VV + (r % VV)], 0.f);
        }
        return;
    }
    extern __shared__ __align__(16) float dsm[];
    float* Hs  = dsm + GHS;    // [cp][v pad28]
    float* As  = dsm + GAS;    // [k][v][w pad28]
    float* Ss  = dsm + GSS;
    float* red = dsm + GRD;
    float* Ws  = dsm + GWS;    // double-buffered weight chunks [2][8*KC]

    int t = blockIdx.x;
    int c = tid & 255;
    int hv = tid >> 8;         // v-half: 0 -> v 0..13, 1 -> v 14..27

    for (int i = tid; i < KK * VV * 28; i += 512) {
        int kv = i / 28, w = i - kv * 28;
        As[i] = (w < VV) ? Aadj[kv * VV + w] * impl[kv * VV + w] : 0.f;
    }

    if (l == 0) {
        const float* Hp = g_H[0] + t * CC * HSTR;
        for (int i = tid; i < CC * HSTR; i += 512) Hs[i] = Hp[i];
    } else {
        // ---- sum 6 k-split z partials; +bias; LN2; residual; ReLU (half 0) ---
        float z[28];
        float s = 0.f, s2 = 0.f;
        if (hv == 0) {
            float btv = btp[c];
            #pragma unroll
            for (int w = 0; w < 28; w++) z[w] = 0.f;
            #pragma unroll
            for (int p = 0; p < KSPL; p++) {
                const float4* zr =
                    reinterpret_cast<const float4*>(&g_Z6[p][(t * CC + c) * HSTR]);
                #pragma unroll
                for (int j = 0; j < 7; j++) {
                    float4 f = zr[j];
                    z[4 * j] += f.x; z[4 * j + 1] += f.y;
                    z[4 * j + 2] += f.z; z[4 * j + 3] += f.w;
                }
            }
            #pragma unroll
            for (int w = 0; w < VV; w++) {
                z[w] += btv;
                s += z[w]; s2 += z[w] * z[w];
            }
        }
        float2 st = ln_stats16(s, s2, red, 1.f / (float)(CC * VV));
        if (hv == 0) {
            const float* Hi = g_H[(l - 1) & 1];
            float* Ho = g_H[l & 1];
            #pragma unroll
            for (int w = 0; w < VV; w++) {
                float val = (z[w] - st.x) * st.y * lw2[c * VV + w] + lb2[c * VV + w];
                float res = (t >= 4) ? Hi[((t - 4) * CC + c) * HSTR + w] : 0.f;
                float h = fmaxf(val + res, 0.f);
                Ho[(t * CC + c) * HSTR + w] = h;
                Hs[c * HSTR + w] = h;
            }
            Hs[c * HSTR + 25] = 0.f;
            Hs[c * HSTR + 26] = 0.f;
            Hs[c * HSTR + 27] = 0.f;
        }
    }
    __syncthreads();
    if (tid < KK * VV) {
        int k = tid / VV, w = tid - k * VV;
        float s = 0.f;
        #pragma unroll
        for (int v = 0; v < VV; v++) s += As[(k * VV + v) * 28 + w];
        Ss[tid] = s;
    }

    // ---- Y[k][v-half] = sum_cp WgT[cp][k*C+c] * H[cp][v-half] ----------------
    // Weights staged through smem, double-buffered, 8 cp-rows per chunk.
    const float* WTl = g_WgT[l];
    {
        const float4* s4 = reinterpret_cast<const float4*>(WTl);
        float4* d4 = reinterpret_cast<float4*>(Ws);
        #pragma unroll
        for (int it = 0; it < 3; it++) d4[tid + it * 512] = s4[tid + it * 512];
    }
    __syncthreads();

    ull Y0[7], Y1[7], Y2[7];
    #pragma unroll
    for (int j = 0; j < 7; j++) { Y0[j] = 0ull; Y1[j] = 0ull; Y2[j] = 0ull; }
    const ull* hbase = reinterpret_cast<const ull*>(Hs) + hv * 7;

    for (int ch = 0; ch < 32; ch++) {
        const float* Wsb = Ws + (ch & 1) * (8 * KC);
        float4 pw[3];
        if (ch < 31) {
            const float4* s4 = reinterpret_cast<const float4*>(WTl + (ch + 1) * 8 * KC);
            #pragma unroll
            for (int it = 0; it < 3; it++) pw[it] = s4[tid + it * 512];
        }
        #pragma unroll
        for (int cpl = 0; cpl < 8; cpl++) {
            float w0 = Wsb[cpl * KC + c];
            float w1 = Wsb[cpl * KC + 256 + c];
            float w2 = Wsb[cpl * KC + 512 + c];
            ull p0 = pack2(w0, w0), p1 = pack2(w1, w1), p2 = pack2(w2, w2);
            const ull* hr = hbase + (ch * 8 + cpl) * 14;
            #pragma unroll
            for (int j = 0; j < 7; j++) {
                ull h = hr[j];
                Y0[j] = fma2(p0, h, Y0[j]);
                Y1[j] = fma2(p1, h, Y1[j]);
                Y2[j] = fma2(p2, h, Y2[j]);
            }
        }
        if (ch < 31) {
            float4* d4 = reinterpret_cast<float4*>(Ws + ((ch & 1) ^ 1) * (8 * KC));
            #pragma unroll
            for (int it = 0; it < 3; it++) d4[tid + it * 512] = pw[it];
        }
        __syncthreads();
    }

    float y[KK][14];
    #pragma unroll
    for (int j = 0; j < 7; j++) {
        float2 a = unpack2(Y0[j]); y[0][2 * j] = a.x; y[0][2 * j + 1] = a.y;
        float2 b = unpack2(Y1[j]); y[1][2 * j] = b.x; y[1][2 * j + 1] = b.y;
        float2 d = unpack2(Y2[j]); y[2][2 * j] = d.x; y[2][2 * j + 1] = d.y;
    }

    // ---- z_partial[w] = sum_k sum_{v in half} y * As[k][v][w] ----------------
    ull zacc[14];
    #pragma unroll
    for (int j = 0; j < 14; j++) zacc[j] = 0ull;
    int vbase = hv * 14;
    int vcnt = hv ? 11 : 14;   // half 1 covers v=14..24 (25..27 are zero-pad)
    #pragma unroll
    for (int k = 0; k < KK; k++) {
        for (int vl = 0; vl < vcnt; vl++) {
            float yv = y[k][vl];
            ull yy = pack2(yv, yv);
            const ull* ar = reinterpret_cast<const ull*>(&As[(k * VV + vbase + vl) * 28]);
            #pragma unroll
            for (int j = 0; j < 14; j++) zacc[j] = fma2(yy, ar[j], zacc[j]);
        }
    }
    float zp[28];
    #pragma unroll
    for (int j = 0; j < 14; j++) {
        float2 a = unpack2(zacc[j]);
        zp[2 * j] = a.x; zp[2 * j + 1] = a.y;
    }
    float* Zs = Hs;   // alias: Hs dead after Y loop
    if (hv == 1) {
        #pragma unroll
        for (int j = 0; j < 7; j++)
            *reinterpret_cast<float4*>(&Zs[c * 28 + 4 * j]) =
                make_float4(zp[4 * j], zp[4 * j + 1], zp[4 * j + 2], zp[4 * j + 3]);
    }
    __syncthreads();
    float s = 0.f, s2 = 0.f;
    float zf[VV];
    if (hv == 0) {
        float b0 = bgl[c], b1 = bgl[CC + c], b2 = bgl[2 * CC + c];
        #pragma unroll
        for (int w = 0; w < VV; w++) {
            float v = zp[w] + Zs[c * 28 + w]
                    + b0 * Ss[w] + b1 * Ss[VV + w] + b2 * Ss[2 * VV + w];
            zf[w] = v;
            s += v; s2 += v * v;
        }
    }
    float2 st = ln_stats16(s, s2, red, 1.f / (float)(CC * VV));
    if (hv == 0) {
        #pragma unroll
        for (int w = 0; w < VV; w++) {
            float u = (zf[w] - st.x) * st.y * lw1[c * VV + w] + lb1[c * VV + w];
            g_U[c * TP * VV + (t + 8) * VV + w] = fmaxf(u, 0.f);
        }
    }
}

// ------- tconv im2col SGEMM: 128o x 128n, 8o x 8n micro, double-buffered ------
// C_part[kz] = WtT[kz-rows][o] @ B;  B[(c,g)][n] = g_U[c*TP*25 + (8-g)*25 + n].
__global__ void __launch_bounds__(256, 2) k_tconv(int l) {
    __shared__ __align__(16) ull  As2[2][KCH][128];   // 32 KB
    __shared__ __align__(16) float Bs[2][KCH][128];   // 16 KB
    int n0 = blockIdx.x * 128, o0 = blockIdx.y * 128;
    int kz = blockIdx.z;
    int kbase = kz * KSEG;
    int tid = threadIdx.x, tx = tid & 15, ty = tid >> 4;
    const ull* WT = g_WtT[l] + (size_t)kbase * CC;

    // prolog: fill stage 0 with tile 0
    {
        int idx = tid;
        #pragma unroll
        for (int it = 0; it < 4; it++, idx += 256) {
            int kk = idx >> 6, oj = (idx & 63) * 2;
            ulonglong2 w = *reinterpret_cast<const ulonglong2*>(
                WT + (size_t)kk * CC + o0 + oj);
            *reinterpret_cast<ulonglong2*>(&As2[0][kk][oj]) = w;
        }
        idx = tid;
        #pragma unroll
        for (int it = 0; it < 2; it++, idx += 256) {
            int kk = idx >> 5, j4 = (idx & 31) * 4;
            int r = kbase + kk;
            int c = r / GG, g = r - c * GG;
            const float* src = g_U + c * (TP * VV) + (8 - g) * VV + n0 + j4;
            *reinterpret_cast<float4*>(&Bs[0][kk][j4]) =
                make_float4(src[0], src[1], src[2], src[3]);
        }
    }
    __syncthreads();

    ull acc[8][4];
    #pragma unroll
    for (int i = 0; i < 8; i++)
        #pragma unroll
        for (int j = 0; j < 4; j++) acc[i][j] = 0ull;

    for (int rt = 0; rt < NSEG; rt++) {
        int cur = rt & 1;
        ulonglong2 pa[4];
        float pb[8];
        if (rt + 1 < NSEG) {
            int r0n = (rt + 1) * KCH;
            int idx = tid;
            #pragma unroll
            for (int it = 0; it < 4; it++, idx += 256) {
                int kk = idx >> 6, oj = (idx & 63) * 2;
                pa[it] = *reinterpret_cast<const ulonglong2*>(
                    WT + (size_t)(r0n + kk) * CC + o0 + oj);
            }
            idx = tid;
            #pragma unroll
            for (int it = 0; it < 2; it++, idx += 256) {
                int kk = idx >> 5, j4 = (idx & 31) * 4;
                int r = kbase + r0n + kk;
                int c = r / GG, g = r - c * GG;
                const float* src = g_U + c * (TP * VV) + (8 - g) * VV + n0 + j4;
                pb[4 * it + 0] = src[0];
                pb[4 * it + 1] = src[1];
                pb[4 * it + 2] = src[2];
                pb[4 * it + 3] = src[3];
            }
        }
        #pragma unroll
        for (int kk = 0; kk < KCH; kk++) {
            ulonglong2 a01 = *reinterpret_cast<const ulonglong2*>(&As2[cur][kk][ty * 8]);
            ulonglong2 a23 = *reinterpret_cast<const ulonglong2*>(&As2[cur][kk][ty * 8 + 2]);
            ulonglong2 a45 = *reinterpret_cast<const ulonglong2*>(&As2[cur][kk][ty * 8 + 4]);
            ulonglong2 a67 = *reinterpret_cast<const ulonglong2*>(&As2[cur][kk][ty * 8 + 6]);
            ulonglong2 b01 = *reinterpret_cast<const ulonglong2*>(&Bs[cur][kk][tx * 8]);
            ulonglong2 b23 = *reinterpret_cast<const ulonglong2*>(&Bs[cur][kk][tx * 8 + 4]);
            ull av[8] = {a01.x, a01.y, a23.x, a23.y, a45.x, a45.y, a67.x, a67.y};
            ull bv[4] = {b01.x, b01.y, b23.x, b23.y};
            #pragma unroll
            for (int i = 0; i < 8; i++)
                #pragma unroll
                for (int j = 0; j < 4; j++)
                    acc[i][j] = fma2(av[i], bv[j], acc[i][j]);
        }
        if (rt + 1 < NSEG) {
            int nxt = cur ^ 1;
            int idx = tid;
            #pragma unroll
            for (int it = 0; it < 4; it++, idx += 256) {
                int kk = idx >> 6, oj = (idx & 63) * 2;
                *reinterpret_cast<ulonglong2*>(&As2[nxt][kk][oj]) = pa[it];
            }
            idx = tid;
            #pragma unroll
            for (int it = 0; it < 2; it++, idx += 256) {
                int kk = idx >> 5, j4 = (idx & 31) * 4;
                *reinterpret_cast<float4*>(&Bs[nxt][kk][j4]) =
                    make_float4(pb[4 * it], pb[4 * it + 1], pb[4 * it + 2], pb[4 * it + 3]);
            }
        }
        __syncthreads();
    }

    float* Zp = g_Z6[kz];
    #pragma unroll
    for (int i = 0; i < 8; i++) {
        int o = o0 + ty * 8 + i;
        #pragma unroll
        for (int j = 0; j < 4; j++) {
            int n = n0 + tx * 8 + 2 * j;
            float2 p = unpack2(acc[i][j]);
            int t = n / VV, v = n - t * VV;
            Zp[(t * CC + o) * HSTR + v] = p.x;
            n++;
            t = n / VV; v = n - t * VV;
            Zp[(t * CC + o) * HSTR + v] = p.y;
        }
    }
}

// ------- final: z + LN2 + residual + ReLU + pool + classify -------------------
__global__ void __launch_bounds__(256) k_out(
    const float* __restrict__ btp, const float* __restrict__ lw2,
    const float* __restrict__ lb2, const float* __restrict__ Wout,
    const float* __restrict__ bout, float* __restrict__ out) {
    int t = blockIdx.x, c = threadIdx.x;
    __shared__ float red[18];
    __shared__ float pooled[CC];
    float z[28];
    #pragma unroll
    for (int w = 0; w < 28; w++) z[w] = 0.f;
    #pragma unroll
    for (int p = 0; p < KSPL; p++) {
        const float4* zr = reinterpret_cast<const float4*>(&g_Z6[p][(t * CC + c) * HSTR]);
        #pragma unroll
        for (int j = 0; j < 7; j++) {
            float4 f = zr[j];
            z[4 * j] += f.x; z[4 * j + 1] += f.y;
            z[4 * j + 2] += f.z; z[4 * j + 3] += f.w;
        }
    }
    float btv = btp[c];
    float s = 0.f, s2 = 0.f;
    #pragma unroll
    for (int w = 0; w < VV; w++) { z[w] += btv; s += z[w]; s2 += z[w] * z[w]; }
    float2 st = ln_stats8(s, s2, red, 1.f / (float)(CC * VV));
    // layer-8 INPUT: written by k_gcn(l=8) to g_H[8&1] = g_H[0]
    const float* Hi = g_H[0];
    float acc = 0.f;
    #pragma unroll
    for (int w = 0; w < VV; w++) {
        float val = (z[w] - st.x) * st.y * lw2[c * VV + w] + lb2[c * VV + w];
        float res = (t >= 4) ? Hi[((t - 4) * CC + c) * HSTR + w] : 0.f;
        acc += fmaxf(val + res, 0.f);
    }
    pooled[c] = acc * (1.f / (float)VV);
    __syncthreads();
    if (c < NCC) {
        float a = bout[c];
        for (int q = 0; q < CC; q++) a = fmaf(Wout[c * CC + q], pooled[q], a);
        out[t * NCC + c] = a;
    }
}

// ------------------------------- launcher -------------------------------------
extern "C" void kernel_launch(void* const* d_in, const int* in_sizes, int n_in,
                              void* d_out, int out_size) {
    const float* x    = (const float*)d_in[0];
    const float* Aadj = (const float*)d_in[1];
    const float* lniw = (const float*)d_in[2];
    const float* lnib = (const float*)d_in[3];
    const float* Win  = (const float*)d_in[4];
    const float* bin  = (const float*)d_in[5];
    const float* Wg   = (const float*)d_in[6];
    const float* bg   = (const float*)d_in[7];
    const float* ln1w = (const float*)d_in[8];
    const float* ln1b = (const float*)d_in[9];
    const float* Wt   = (const float*)d_in[10];
    const float* bt   = (const float*)d_in[11];
    const float* ln2w = (const float*)d_in[12];
    const float* ln2b = (const float*)d_in[13];
    const float* imp  = (const float*)d_in[14];
    const float* Wout = (const float*)d_in[15];
    const float* bout = (const float*)d_in[16];
    float* out = (float*)d_out;

    cudaFuncSetAttribute(k_gcn, cudaFuncAttributeMaxDynamicSharedMemorySize, GSM_BYTES);

    k_wgt<<<dim3(24, 8, LL), dim3(32, 8)>>>(Wg);
    k_wtt<<<dim3(72, 8, LL), dim3(32, 8)>>>(Wt);
    k_input<<<TT, 256>>>(x, lniw, lnib, Win, bin);
    for (int l = 0; l < LL; l++) {
        int p = (l > 0) ? (l - 1) : 0;
        k_gcn<<<TT + 1, 512, GSM_BYTES>>>(l, bg + l * KC, Aadj, imp + l * KK * VV * VV,
                                          ln1w + l * CC * VV, ln1b + l * CC * VV,
                                          bt + p * CC, ln2w + p * CC * VV,
                                          ln2b + p * CC * VV);
        k_tconv<<<dim3(25, 2, KSPL), 256>>>(l);
    }
    k_out<<<TT, 256>>>(bt + 8 * CC, ln2w + 8 * CC * VV, ln2b + 8 * CC * VV,
                       Wout, bout, out);
}